// round 4
// baseline (speedup 1.0000x reference)
#include <cuda_runtime.h>

// Problem constants
#define S_TOTAL    37448       // sum of LAYER_SIZES
#define OUT_TOKENS 5704        // 8 + 64 + 512 + 1024 + 4096
#define BATCH      8
#define NROWS      196         // 4 val rows + 3*64 pos rows
#define PR_ROWS    7           // rows per projection block (28 chunks)

// conv smem-table geometry
#define C4_STRIDE  36          // 32-float o-slice + pad (144B, 16B aligned)
#define C4_SMEM    (8 * NROWS * C4_STRIDE * 4)      // 225792 B
#define C4_CHUNKS  18
#define C4_TPB     1821        // ceil(32768/18)
#define C3_STRIDE  68          // 64-float o-slice + pad (272B, 16B aligned)
#define C3_SMEM    (4 * NROWS * C3_STRIDE * 4)      // 213248 B
#define C3_CHUNKS  37
#define C3_TPB     222         // ceil(8192/37)

// Scratch (static device globals; no runtime allocation)
__device__ float g_Wt3[4 * 256 * 256];        // [kk][e][o]
__device__ float g_Wt4[8 * 256 * 256];
__device__ float g_proj3[4 * NROWS * 256];    // [kk][row][o]
__device__ float g_proj4[8 * NROWS * 256];

// ---------------------------------------------------------------------------
// Kernel A: tiled transpose  W[o][e][kk] -> Wt[kk][e][o]
// ---------------------------------------------------------------------------
template <int K>
__global__ void __launch_bounds__(256) transpose_w_tiled(const float* __restrict__ W) {
    constexpr int TO  = (K == 4) ? 64 : 32;
    constexpr int TE  = 32;
    constexpr int PAD = TO + 1;
    float* Wt = (K == 4) ? g_Wt3 : g_Wt4;

    __shared__ float sm[K][TE][PAD];

    int o0 = (blockIdx.x % (256 / TO)) * TO;
    int e0 = (blockIdx.x / (256 / TO)) * TE;

    const float4* Wv = reinterpret_cast<const float4*>(W);

    for (int i = threadIdx.x; i < TO * TE; i += 256) {
        int o_l = i / TE;
        int e_l = i % TE;
        int idx = (o0 + o_l) * 256 + (e0 + e_l);
#pragma unroll
        for (int q = 0; q < K / 4; q++) {
            float4 v = Wv[idx * (K / 4) + q];
            sm[q * 4 + 0][e_l][o_l] = v.x;
            sm[q * 4 + 1][e_l][o_l] = v.y;
            sm[q * 4 + 2][e_l][o_l] = v.z;
            sm[q * 4 + 3][e_l][o_l] = v.w;
        }
    }
    __syncthreads();

    for (int i = threadIdx.x; i < K * TE * TO; i += 256) {
        int kk  = i / (TE * TO);
        int rem = i % (TE * TO);
        int e_l = rem / TO;
        int o_l = rem % TO;
        Wt[kk * 65536 + (e0 + e_l) * 256 + (o0 + o_l)] = sm[kk][e_l][o_l];
    }
}

// ---------------------------------------------------------------------------
// Kernel B: fused projection for all 12 kk-slices. (unchanged, passing)
// ---------------------------------------------------------------------------
__global__ void __launch_bounds__(256) project_all_kernel(
    const float* __restrict__ val3, const float* __restrict__ pos3,
    const float* __restrict__ val4, const float* __restrict__ pos4)
{
    int s  = blockIdx.y;
    int r0 = blockIdx.x * PR_ROWS;

    const float* Wt; float* proj; const float* ve; const float* pe;
    if (s < 4) { Wt = g_Wt3 + s * 65536;        proj = g_proj3 + s * (NROWS * 256);
                 ve = val3; pe = pos3; }
    else       { int kk = s - 4;
                 Wt = g_Wt4 + kk * 65536;       proj = g_proj4 + kk * (NROWS * 256);
                 ve = val4; pe = pos4; }

    int o4 = threadIdx.x & 63;
    int eh = threadIdx.x >> 6;
    int ebase = eh * 64;

    __shared__ float  srow[PR_ROWS][256];
    __shared__ float4 sred[3][PR_ROWS][64];

    for (int i = threadIdx.x; i < PR_ROWS * 256; i += 256) {
        int r = i >> 8, c = i & 255;
        int rr = r0 + r;
        srow[r][c] = (rr < 4) ? ve[rr * 256 + c] : pe[(rr - 4) * 256 + c];
    }
    __syncthreads();

    float4 acc[PR_ROWS];
#pragma unroll
    for (int r = 0; r < PR_ROWS; r++) acc[r] = make_float4(0.f, 0.f, 0.f, 0.f);

    const float4* Wv = reinterpret_cast<const float4*>(Wt);
#pragma unroll 8
    for (int e = 0; e < 64; e++) {
        float4 w = Wv[(ebase + e) * 64 + o4];
#pragma unroll
        for (int r = 0; r < PR_ROWS; r++) {
            float x = srow[r][ebase + e];
            acc[r].x += x * w.x; acc[r].y += x * w.y;
            acc[r].z += x * w.z; acc[r].w += x * w.w;
        }
    }

    if (eh > 0) {
#pragma unroll
        for (int r = 0; r < PR_ROWS; r++) sred[eh - 1][r][o4] = acc[r];
    }
    __syncthreads();
    if (eh == 0) {
#pragma unroll
        for (int r = 0; r < PR_ROWS; r++) {
            float4 a = acc[r];
            float4 b0 = sred[0][r][o4], b1 = sred[1][r][o4], b2 = sred[2][r][o4];
            a.x += b0.x + b1.x + b2.x;
            a.y += b0.y + b1.y + b2.y;
            a.z += b0.z + b1.z + b2.z;
            a.w += b0.w + b1.w + b2.w;
            reinterpret_cast<float4*>(proj)[(r0 + r) * 64 + o4] = a;
        }
    }
}

// ---------------------------------------------------------------------------
// Kernel C: layers 0-2 (pure embedding sum). (unchanged, passing)
// ---------------------------------------------------------------------------
__global__ void __launch_bounds__(256) embed_small_kernel(
    const int* __restrict__ value,
    const int* __restrict__ depth,
    const int* __restrict__ position,
    const float* __restrict__ v0, const float* __restrict__ v1, const float* __restrict__ v2,
    const float* __restrict__ p0, const float* __restrict__ p1, const float* __restrict__ p2,
    const float* __restrict__ d0, const float* __restrict__ d1, const float* __restrict__ d2,
    float* __restrict__ out)
{
    int idx = blockIdx.x * blockDim.x + threadIdx.x;
    int lane  = idx & 63;
    int token = idx >> 6;
    if (token >= BATCH * 584) return;
    int b = token / 584;
    int s = token % 584;

    const float *ve, *pe, *de;
    if (s < 8)       { ve = v0; pe = p0; de = d0; }
    else if (s < 72) { ve = v1; pe = p1; de = d1; }
    else             { ve = v2; pe = p2; de = d2; }

    int base = b * S_TOTAL + s;
    int v = value[base];
    int d = depth[base];
    const int* pp = position + base * 3;
    int q0 = pp[0], q1 = pp[1], q2 = pp[2];

    const float4* V  = reinterpret_cast<const float4*>(ve) + v * 64 + lane;
    const float4* P0 = reinterpret_cast<const float4*>(pe) + (q0)       * 64 + lane;
    const float4* P1 = reinterpret_cast<const float4*>(pe) + (64 + q1)  * 64 + lane;
    const float4* P2 = reinterpret_cast<const float4*>(pe) + (128 + q2) * 64 + lane;
    const float4* D  = reinterpret_cast<const float4*>(de) + d * 64 + lane;

    float4 a = *V, x;
    x = *P0; a.x += x.x; a.y += x.y; a.z += x.z; a.w += x.w;
    x = *P1; a.x += x.x; a.y += x.y; a.z += x.z; a.w += x.w;
    x = *P2; a.x += x.x; a.y += x.y; a.z += x.z; a.w += x.w;
    x = *D;  a.x += x.x; a.y += x.y; a.z += x.z; a.w += x.w;

    reinterpret_cast<float4*>(out)[(b * OUT_TOKENS + s) * 64 + lane] = a;
}

// ---------------------------------------------------------------------------
// Kernel D4: layer-4 conv via smem-resident o-sliced table.
// grid = (C4_CHUNKS, 8 o-slices); block 256 = 32 token-groups x 8 lanes.
// ---------------------------------------------------------------------------
__global__ void __launch_bounds__(256) conv4_smem_kernel(
    const int* __restrict__ value,
    const int* __restrict__ position,
    const float* __restrict__ bias,
    float* __restrict__ out)
{
    extern __shared__ float tb[];   // [8][196][C4_STRIDE]
    int oslice = blockIdx.y;        // 0..7 (32-float slice)
    int o0 = oslice * 32;

    // Stage table slice: coalesced reads from g_proj4
    for (int i = threadIdx.x; i < 8 * NROWS * 32; i += 256) {
        int row = i >> 5;           // kk*196 + r
        int o   = i & 31;
        tb[row * C4_STRIDE + o] = g_proj4[row * 256 + o0 + o];
    }
    __syncthreads();

    int sub = threadIdx.x & 7;      // lane within token (float4 over o-slice)
    int grp = threadIdx.x >> 3;     // token group 0..31

    float4 bb = reinterpret_cast<const float4*>(bias)[oslice * 8 + sub];

    int t0   = blockIdx.x * C4_TPB;
    int tend = t0 + C4_TPB;
    if (tend > 32768) tend = 32768;

    for (int t = t0 + grp; t < tend; t += 32) {
        int b  = t >> 12;
        int tt = t & 4095;
        int s  = b * S_TOTAL + 4680 + tt * 8 + sub;   // this lane's kk = sub

        int v = value[s];
        const int* pp = position + s * 3;
        int q0 = pp[0], q1 = pp[1], q2 = pp[2];

        float4 acc = bb;
#pragma unroll
        for (int kk = 0; kk < 8; kk++) {
            int rv  = __shfl_sync(0xffffffffu, v,  kk, 8);
            int rq0 = __shfl_sync(0xffffffffu, q0, kk, 8);
            int rq1 = __shfl_sync(0xffffffffu, q1, kk, 8);
            int rq2 = __shfl_sync(0xffffffffu, q2, kk, 8);

            const float* base = tb + kk * (NROWS * C4_STRIDE) + sub * 4;
            float4 x;
            x = *reinterpret_cast<const float4*>(base + rv * C4_STRIDE);
            acc.x += x.x; acc.y += x.y; acc.z += x.z; acc.w += x.w;
            x = *reinterpret_cast<const float4*>(base + (4 + rq0) * C4_STRIDE);
            acc.x += x.x; acc.y += x.y; acc.z += x.z; acc.w += x.w;
            x = *reinterpret_cast<const float4*>(base + (68 + rq1) * C4_STRIDE);
            acc.x += x.x; acc.y += x.y; acc.z += x.z; acc.w += x.w;
            x = *reinterpret_cast<const float4*>(base + (132 + rq2) * C4_STRIDE);
            acc.x += x.x; acc.y += x.y; acc.z += x.z; acc.w += x.w;
        }

        int row = b * OUT_TOKENS + 1608 + tt;
        reinterpret_cast<float4*>(out)[row * 64 + oslice * 8 + sub] = acc;
    }
}

// ---------------------------------------------------------------------------
// Kernel D3: layer-3 conv via smem-resident o-sliced table.
// grid = (C3_CHUNKS, 4 o-slices); block 256 = 16 token-groups x 16 lanes.
// ---------------------------------------------------------------------------
__global__ void __launch_bounds__(256) conv3_smem_kernel(
    const int* __restrict__ value,
    const int* __restrict__ position,
    const float* __restrict__ bias,
    float* __restrict__ out)
{
    extern __shared__ float tb[];   // [4][196][C3_STRIDE]
    int oslice = blockIdx.y;        // 0..3 (64-float slice)
    int o0 = oslice * 64;

    for (int i = threadIdx.x; i < 4 * NROWS * 64; i += 256) {
        int row = i >> 6;           // kk*196 + r
        int o   = i & 63;
        tb[row * C3_STRIDE + o] = g_proj3[row * 256 + o0 + o];
    }
    __syncthreads();

    int sub = threadIdx.x & 15;     // lane within token
    int grp = threadIdx.x >> 4;     // token group 0..15

    float4 bb = reinterpret_cast<const float4*>(bias)[oslice * 16 + sub];

    int t0   = blockIdx.x * C3_TPB;
    int tend = t0 + C3_TPB;
    if (tend > 8192) tend = 8192;

    for (int t = t0 + grp; t < tend; t += 16) {
        int b  = t >> 10;
        int tt = t & 1023;
        int s  = b * S_TOTAL + 584 + tt * 4 + (sub & 3);  // lanes 0-3 carry kk data

        int v = value[s];
        const int* pp = position + s * 3;
        int q0 = pp[0], q1 = pp[1], q2 = pp[2];

        float4 acc = bb;
#pragma unroll
        for (int kk = 0; kk < 4; kk++) {
            int rv  = __shfl_sync(0xffffffffu, v,  kk, 16);
            int rq0 = __shfl_sync(0xffffffffu, q0, kk, 16);
            int rq1 = __shfl_sync(0xffffffffu, q1, kk, 16);
            int rq2 = __shfl_sync(0xffffffffu, q2, kk, 16);

            const float* base = tb + kk * (NROWS * C3_STRIDE) + sub * 4;
            float4 x;
            x = *reinterpret_cast<const float4*>(base + rv * C3_STRIDE);
            acc.x += x.x; acc.y += x.y; acc.z += x.z; acc.w += x.w;
            x = *reinterpret_cast<const float4*>(base + (4 + rq0) * C3_STRIDE);
            acc.x += x.x; acc.y += x.y; acc.z += x.z; acc.w += x.w;
            x = *reinterpret_cast<const float4*>(base + (68 + rq1) * C3_STRIDE);
            acc.x += x.x; acc.y += x.y; acc.z += x.z; acc.w += x.w;
            x = *reinterpret_cast<const float4*>(base + (132 + rq2) * C3_STRIDE);
            acc.x += x.x; acc.y += x.y; acc.z += x.z; acc.w += x.w;
        }

        int row = b * OUT_TOKENS + 584 + tt;
        reinterpret_cast<float4*>(out)[row * 64 + oslice * 16 + sub] = acc;
    }
}

// ---------------------------------------------------------------------------
// Launch. Inputs classified BY ELEMENT COUNT (robust to metadata ordering).
// ---------------------------------------------------------------------------
extern "C" void kernel_launch(void* const* d_in, const int* in_sizes, int n_in,
                              void* d_out, int out_size) {
    const int* value = nullptr;
    const int* depth = nullptr;
    const int* position = nullptr;
    const float* val_emb[5] = {};
    const float* pos_emb[5] = {};
    const float* dep_emb[3] = {};
    const float* conv_w3 = nullptr;
    const float* conv_w4 = nullptr;
    const float* conv_b3 = nullptr;
    const float* conv_b4 = nullptr;

    int n_val = 0, n_pos = 0, n_dep = 0, n_cb = 0, n_vd = 0;
    for (int i = 0; i < n_in; i++) {
        int sz = in_sizes[i];
        const void* p = d_in[i];
        switch (sz) {
            case 299584:
                if (n_vd++ == 0) value = (const int*)p; else depth = (const int*)p;
                break;
            case 898752:  position = (const int*)p; break;
            case 1024:    if (n_val < 5) val_emb[n_val++] = (const float*)p; break;
            case 49152:   if (n_pos < 5) pos_emb[n_pos++] = (const float*)p; break;
            case 1536:    if (n_dep < 3) dep_emb[n_dep++] = (const float*)p; break;
            case 262144:  conv_w3 = (const float*)p; break;
            case 524288:  conv_w4 = (const float*)p; break;
            case 256:
                if (n_cb++ == 0) conv_b3 = (const float*)p; else conv_b4 = (const float*)p;
                break;
            default: break;
        }
    }

    float* out = (float*)d_out;

    // Opt in to large dynamic smem (idempotent host-side calls, capture-safe)
    static bool attr_done = false;
    if (!attr_done) {
        cudaFuncSetAttribute(conv4_smem_kernel,
                             cudaFuncAttributeMaxDynamicSharedMemorySize, C4_SMEM);
        cudaFuncSetAttribute(conv3_smem_kernel,
                             cudaFuncAttributeMaxDynamicSharedMemorySize, C3_SMEM);
        attr_done = true;
    }

    // A: tiled transposes
    transpose_w_tiled<4><<<(256 / 64) * (256 / 32), 256>>>(conv_w3);
    transpose_w_tiled<8><<<(256 / 32) * (256 / 32), 256>>>(conv_w4);

    // B: fused projection, all 12 kk-slices
    project_all_kernel<<<dim3(NROWS / PR_ROWS, 12), 256>>>(
        val_emb[3], pos_emb[3], val_emb[4], pos_emb[4]);

    // C: small layers 0-2
    {
        int threads = BATCH * 584 * 64;
        embed_small_kernel<<<(threads + 255) / 256, 256>>>(
            value, depth, position,
            val_emb[0], val_emb[1], val_emb[2],
            pos_emb[0], pos_emb[1], pos_emb[2],
            dep_emb[0], dep_emb[1], dep_emb[2],
            out);
    }

    // D: conv layers via smem-resident table slices
    conv3_smem_kernel<<<dim3(C3_CHUNKS, 4), 256, C3_SMEM>>>(
        value, position, conv_b3, out);
    conv4_smem_kernel<<<dim3(C4_CHUNKS, 8), 256, C4_SMEM>>>(
        value, position, conv_b4, out);
}

// round 6
// speedup vs baseline: 1.8718x; 1.8718x over previous
#include <cuda_runtime.h>
#include <cuda_fp16.h>

// Problem constants
#define S_TOTAL    37448       // sum of LAYER_SIZES
#define OUT_TOKENS 5704        // 8 + 64 + 512 + 1024 + 4096
#define BATCH      8
#define NROWS      196         // 4 val rows + 3*64 pos rows
#define PR_ROWS    7           // rows per projection block (28 chunks)

// Scratch (static device globals; no runtime allocation)
__device__ float  g_Wt3[4 * 256 * 256];          // [kk][e][o]
__device__ float  g_Wt4[8 * 256 * 256];
__device__ __half g_proj3h[4 * NROWS * 256];     // [kk][row][o]  fp16 tables
__device__ __half g_proj4h[8 * NROWS * 256];

// ---------------------------------------------------------------------------
// Kernel A: tiled transpose  W[o][e][kk] -> Wt[kk][e][o]
// ---------------------------------------------------------------------------
template <int K>
__global__ void __launch_bounds__(256) transpose_w_tiled(const float* __restrict__ W) {
    constexpr int TO  = (K == 4) ? 64 : 32;
    constexpr int TE  = 32;
    constexpr int PAD = TO + 1;
    float* Wt = (K == 4) ? g_Wt3 : g_Wt4;

    __shared__ float sm[K][TE][PAD];

    int o0 = (blockIdx.x % (256 / TO)) * TO;
    int e0 = (blockIdx.x / (256 / TO)) * TE;

    const float4* Wv = reinterpret_cast<const float4*>(W);

    for (int i = threadIdx.x; i < TO * TE; i += 256) {
        int o_l = i / TE;
        int e_l = i % TE;
        int idx = (o0 + o_l) * 256 + (e0 + e_l);
#pragma unroll
        for (int q = 0; q < K / 4; q++) {
            float4 v = Wv[idx * (K / 4) + q];
            sm[q * 4 + 0][e_l][o_l] = v.x;
            sm[q * 4 + 1][e_l][o_l] = v.y;
            sm[q * 4 + 2][e_l][o_l] = v.z;
            sm[q * 4 + 3][e_l][o_l] = v.w;
        }
    }
    __syncthreads();

    for (int i = threadIdx.x; i < K * TE * TO; i += 256) {
        int kk  = i / (TE * TO);
        int rem = i % (TE * TO);
        int e_l = rem / TO;
        int o_l = rem % TO;
        Wt[kk * 65536 + (e0 + e_l) * 256 + (o0 + o_l)] = sm[kk][e_l][o_l];
    }
}

// ---------------------------------------------------------------------------
// Kernel B: fused projection for all 12 kk-slices; emits fp16 tables.
// proj[kk][r][o] = sum_e emb_row_r[e] * Wt[kk][e][o]
// ---------------------------------------------------------------------------
__global__ void __launch_bounds__(256) project_all_kernel(
    const float* __restrict__ val3, const float* __restrict__ pos3,
    const float* __restrict__ val4, const float* __restrict__ pos4)
{
    int s  = blockIdx.y;            // slice 0..11 (0-3 -> layer3, 4-11 -> layer4)
    int r0 = blockIdx.x * PR_ROWS;

    const float* Wt; __half* proj; const float* ve; const float* pe;
    if (s < 4) { Wt = g_Wt3 + s * 65536;        proj = g_proj3h + s * (NROWS * 256);
                 ve = val3; pe = pos3; }
    else       { int kk = s - 4;
                 Wt = g_Wt4 + kk * 65536;       proj = g_proj4h + kk * (NROWS * 256);
                 ve = val4; pe = pos4; }

    int o4 = threadIdx.x & 63;
    int eh = threadIdx.x >> 6;
    int ebase = eh * 64;

    __shared__ float  srow[PR_ROWS][256];
    __shared__ float4 sred[3][PR_ROWS][64];

    for (int i = threadIdx.x; i < PR_ROWS * 256; i += 256) {
        int r = i >> 8, c = i & 255;
        int rr = r0 + r;
        srow[r][c] = (rr < 4) ? ve[rr * 256 + c] : pe[(rr - 4) * 256 + c];
    }
    __syncthreads();

    float4 acc[PR_ROWS];
#pragma unroll
    for (int r = 0; r < PR_ROWS; r++) acc[r] = make_float4(0.f, 0.f, 0.f, 0.f);

    const float4* Wv = reinterpret_cast<const float4*>(Wt);
#pragma unroll 8
    for (int e = 0; e < 64; e++) {
        float4 w = Wv[(ebase + e) * 64 + o4];
#pragma unroll
        for (int r = 0; r < PR_ROWS; r++) {
            float x = srow[r][ebase + e];
            acc[r].x += x * w.x; acc[r].y += x * w.y;
            acc[r].z += x * w.z; acc[r].w += x * w.w;
        }
    }

    if (eh > 0) {
#pragma unroll
        for (int r = 0; r < PR_ROWS; r++) sred[eh - 1][r][o4] = acc[r];
    }
    __syncthreads();
    if (eh == 0) {
#pragma unroll
        for (int r = 0; r < PR_ROWS; r++) {
            float4 a = acc[r];
            float4 b0 = sred[0][r][o4], b1 = sred[1][r][o4], b2 = sred[2][r][o4];
            a.x += b0.x + b1.x + b2.x;
            a.y += b0.y + b1.y + b2.y;
            a.z += b0.z + b1.z + b2.z;
            a.w += b0.w + b1.w + b2.w;
            __half2* dst = reinterpret_cast<__half2*>(proj + (r0 + r) * 256 + o4 * 4);
            dst[0] = __floats2half2_rn(a.x, a.y);
            dst[1] = __floats2half2_rn(a.z, a.w);
        }
    }
}

// ---------------------------------------------------------------------------
// Kernel C: layers 0-2 (pure embedding sum), fp32 exact. (unchanged, passing)
// ---------------------------------------------------------------------------
__global__ void __launch_bounds__(256) embed_small_kernel(
    const int* __restrict__ value,
    const int* __restrict__ depth,
    const int* __restrict__ position,
    const float* __restrict__ v0, const float* __restrict__ v1, const float* __restrict__ v2,
    const float* __restrict__ p0, const float* __restrict__ p1, const float* __restrict__ p2,
    const float* __restrict__ d0, const float* __restrict__ d1, const float* __restrict__ d2,
    float* __restrict__ out)
{
    int idx = blockIdx.x * blockDim.x + threadIdx.x;
    int lane  = idx & 63;
    int token = idx >> 6;
    if (token >= BATCH * 584) return;
    int b = token / 584;
    int s = token % 584;

    const float *ve, *pe, *de;
    if (s < 8)       { ve = v0; pe = p0; de = d0; }
    else if (s < 72) { ve = v1; pe = p1; de = d1; }
    else             { ve = v2; pe = p2; de = d2; }

    int base = b * S_TOTAL + s;
    int v = value[base];
    int d = depth[base];
    const int* pp = position + base * 3;
    int q0 = pp[0], q1 = pp[1], q2 = pp[2];

    const float4* V  = reinterpret_cast<const float4*>(ve) + v * 64 + lane;
    const float4* P0 = reinterpret_cast<const float4*>(pe) + (q0)       * 64 + lane;
    const float4* P1 = reinterpret_cast<const float4*>(pe) + (64 + q1)  * 64 + lane;
    const float4* P2 = reinterpret_cast<const float4*>(pe) + (128 + q2) * 64 + lane;
    const float4* D  = reinterpret_cast<const float4*>(de) + d * 64 + lane;

    float4 a = *V, x;
    x = *P0; a.x += x.x; a.y += x.y; a.z += x.z; a.w += x.w;
    x = *P1; a.x += x.x; a.y += x.y; a.z += x.z; a.w += x.w;
    x = *P2; a.x += x.x; a.y += x.y; a.z += x.z; a.w += x.w;
    x = *D;  a.x += x.x; a.y += x.y; a.z += x.z; a.w += x.w;

    reinterpret_cast<float4*>(out)[(b * OUT_TOKENS + s) * 64 + lane] = a;
}

// ---------------------------------------------------------------------------
// Kernel D: conv layers via fp16 projected-table gathers.
// warp = one token: 32 lanes x 16B = one 512B fp16 row, coalesced.
// Index loads are warp-uniform (1 transaction). Accumulate fp32.
// ---------------------------------------------------------------------------
template <int K>
__global__ void __launch_bounds__(256) conv_half_kernel(
    const int* __restrict__ value,
    const int* __restrict__ position,
    const float* __restrict__ bias,
    float* __restrict__ out,
    int in_start, int out_row_start, int t_per_b)
{
    const __half* proj = (K == 4) ? g_proj3h : g_proj4h;

    int gwarp = (blockIdx.x * blockDim.x + threadIdx.x) >> 5;
    int lane  = threadIdx.x & 31;
    if (gwarp >= BATCH * t_per_b) return;
    int b = gwarp / t_per_b;
    int t = gwarp % t_per_b;

    int sbase = b * S_TOTAL + in_start + t * K;

    // 8 fp32 accumulators (o = lane*8 .. lane*8+7), init with bias
    float acc[8];
    {
        const float4* bv = reinterpret_cast<const float4*>(bias);
        float4 b0 = bv[lane * 2], b1 = bv[lane * 2 + 1];
        acc[0] = b0.x; acc[1] = b0.y; acc[2] = b0.z; acc[3] = b0.w;
        acc[4] = b1.x; acc[5] = b1.y; acc[6] = b1.z; acc[7] = b1.w;
    }

#pragma unroll
    for (int kk = 0; kk < K; kk++) {
        int s = sbase + kk;
        int v = value[s];
        const int* pp = position + s * 3;
        int q0 = pp[0], q1 = pp[1], q2 = pp[2];

        // Row stride = 256 halves = 32 uint4; lane picks its 16B chunk.
        const uint4* P = reinterpret_cast<const uint4*>(proj + kk * (NROWS * 256));
        int rows[4] = { v, 4 + q0, 68 + q1, 132 + q2 };
#pragma unroll
        for (int g = 0; g < 4; g++) {
            uint4 u = P[rows[g] * 32 + lane];
            __half2 h; float2 f;
            h = *reinterpret_cast<const __half2*>(&u.x); f = __half22float2(h);
            acc[0] += f.x; acc[1] += f.y;
            h = *reinterpret_cast<const __half2*>(&u.y); f = __half22float2(h);
            acc[2] += f.x; acc[3] += f.y;
            h = *reinterpret_cast<const __half2*>(&u.z); f = __half22float2(h);
            acc[4] += f.x; acc[5] += f.y;
            h = *reinterpret_cast<const __half2*>(&u.w); f = __half22float2(h);
            acc[6] += f.x; acc[7] += f.y;
        }
    }

    int row = b * OUT_TOKENS + out_row_start + t;
    float4* dst = reinterpret_cast<float4*>(out + row * 256 + lane * 8);
    dst[0] = make_float4(acc[0], acc[1], acc[2], acc[3]);
    dst[1] = make_float4(acc[4], acc[5], acc[6], acc[7]);
}

// ---------------------------------------------------------------------------
// Launch. Inputs classified BY ELEMENT COUNT (robust to metadata ordering).
// Launch order puts conv4 in the ncu capture slot.
// ---------------------------------------------------------------------------
extern "C" void kernel_launch(void* const* d_in, const int* in_sizes, int n_in,
                              void* d_out, int out_size) {
    const int* value = nullptr;
    const int* depth = nullptr;
    const int* position = nullptr;
    const float* val_emb[5] = {};
    const float* pos_emb[5] = {};
    const float* dep_emb[3] = {};
    const float* conv_w3 = nullptr;
    const float* conv_w4 = nullptr;
    const float* conv_b3 = nullptr;
    const float* conv_b4 = nullptr;

    int n_val = 0, n_pos = 0, n_dep = 0, n_cb = 0, n_vd = 0;
    for (int i = 0; i < n_in; i++) {
        int sz = in_sizes[i];
        const void* p = d_in[i];
        switch (sz) {
            case 299584:
                if (n_vd++ == 0) value = (const int*)p; else depth = (const int*)p;
                break;
            case 898752:  position = (const int*)p; break;
            case 1024:    if (n_val < 5) val_emb[n_val++] = (const float*)p; break;
            case 49152:   if (n_pos < 5) pos_emb[n_pos++] = (const float*)p; break;
            case 1536:    if (n_dep < 3) dep_emb[n_dep++] = (const float*)p; break;
            case 262144:  conv_w3 = (const float*)p; break;
            case 524288:  conv_w4 = (const float*)p; break;
            case 256:
                if (n_cb++ == 0) conv_b3 = (const float*)p; else conv_b4 = (const float*)p;
                break;
            default: break;
        }
    }

    float* out = (float*)d_out;

    // A: tiled transposes
    transpose_w_tiled<4><<<(256 / 64) * (256 / 32), 256>>>(conv_w3);
    transpose_w_tiled<8><<<(256 / 32) * (256 / 32), 256>>>(conv_w4);

    // B: fused projection -> fp16 tables
    project_all_kernel<<<dim3(NROWS / PR_ROWS, 12), 256>>>(
        val_emb[3], pos_emb[3], val_emb[4], pos_emb[4]);

    // D4 first (lands in the ncu capture slot): 32768 token-warps
    {
        int warps4 = BATCH * 4096;
        conv_half_kernel<8><<<(warps4 * 32 + 255) / 256, 256>>>(
            value, position, conv_b4, out,
            /*in_start=*/4680, /*out_row_start=*/1608, /*t_per_b=*/4096);
    }

    // D3: 8192 token-warps
    {
        int warps3 = BATCH * 1024;
        conv_half_kernel<4><<<(warps3 * 32 + 255) / 256, 256>>>(
            value, position, conv_b3, out,
            /*in_start=*/584, /*out_row_start=*/584, /*t_per_b=*/1024);
    }

    // C: small layers 0-2
    {
        int threads = BATCH * 584 * 64;
        embed_small_kernel<<<(threads + 255) / 256, 256>>>(
            value, depth, position,
            val_emb[0], val_emb[1], val_emb[2],
            pos_emb[0], pos_emb[1], pos_emb[2],
            dep_emb[0], dep_emb[1], dep_emb[2],
            out);
    }
}

// round 7
// speedup vs baseline: 2.0695x; 1.1056x over previous
#include <cuda_runtime.h>
#include <cuda_fp16.h>

// Problem constants
#define S_TOTAL    37448       // sum of LAYER_SIZES
#define OUT_TOKENS 5704        // 8 + 64 + 512 + 1024 + 4096
#define BATCH      8
#define NROWS      196         // 4 val rows + 3*64 pos rows
#define PR_ROWS    4           // rows per projection block (49 chunks, ~4 waves)

// Scratch (static device globals; no runtime allocation)
__device__ float  g_Wt3[4 * 256 * 256];          // [kk][e][o]
__device__ float  g_Wt4[8 * 256 * 256];
__device__ __half g_proj3h[4 * NROWS * 256];     // [kk][row][o]  fp16 tables
__device__ __half g_proj4h[8 * NROWS * 256];

// ---------------------------------------------------------------------------
// Kernel A: tiled transpose  W[o][e][kk] -> Wt[kk][e][o]
// ---------------------------------------------------------------------------
template <int K>
__global__ void __launch_bounds__(256) transpose_w_tiled(const float* __restrict__ W) {
    constexpr int TO  = (K == 4) ? 64 : 32;
    constexpr int TE  = 32;
    constexpr int PAD = TO + 1;
    float* Wt = (K == 4) ? g_Wt3 : g_Wt4;

    __shared__ float sm[K][TE][PAD];

    int o0 = (blockIdx.x % (256 / TO)) * TO;
    int e0 = (blockIdx.x / (256 / TO)) * TE;

    const float4* Wv = reinterpret_cast<const float4*>(W);

    for (int i = threadIdx.x; i < TO * TE; i += 256) {
        int o_l = i / TE;
        int e_l = i % TE;
        int idx = (o0 + o_l) * 256 + (e0 + e_l);
#pragma unroll
        for (int q = 0; q < K / 4; q++) {
            float4 v = Wv[idx * (K / 4) + q];
            sm[q * 4 + 0][e_l][o_l] = v.x;
            sm[q * 4 + 1][e_l][o_l] = v.y;
            sm[q * 4 + 2][e_l][o_l] = v.z;
            sm[q * 4 + 3][e_l][o_l] = v.w;
        }
    }
    __syncthreads();

    for (int i = threadIdx.x; i < K * TE * TO; i += 256) {
        int kk  = i / (TE * TO);
        int rem = i % (TE * TO);
        int e_l = rem / TO;
        int o_l = rem % TO;
        Wt[kk * 65536 + (e0 + e_l) * 256 + (o0 + o_l)] = sm[kk][e_l][o_l];
    }
}

// ---------------------------------------------------------------------------
// Kernel B: fused projection for all 12 kk-slices; emits fp16 tables.
// proj[kk][r][o] = sum_e emb_row_r[e] * Wt[kk][e][o]
// grid = (49 row-chunks, 12 slices); block 256 = 64 o-quads x 4 e-quarters.
// ---------------------------------------------------------------------------
__global__ void __launch_bounds__(256) project_all_kernel(
    const float* __restrict__ val3, const float* __restrict__ pos3,
    const float* __restrict__ val4, const float* __restrict__ pos4)
{
    int s  = blockIdx.y;            // slice 0..11 (0-3 -> layer3, 4-11 -> layer4)
    int r0 = blockIdx.x * PR_ROWS;

    const float* Wt; __half* proj; const float* ve; const float* pe;
    if (s < 4) { Wt = g_Wt3 + s * 65536;        proj = g_proj3h + s * (NROWS * 256);
                 ve = val3; pe = pos3; }
    else       { int kk = s - 4;
                 Wt = g_Wt4 + kk * 65536;       proj = g_proj4h + kk * (NROWS * 256);
                 ve = val4; pe = pos4; }

    int o4 = threadIdx.x & 63;
    int eh = threadIdx.x >> 6;
    int ebase = eh * 64;

    __shared__ float  srow[PR_ROWS][256];
    __shared__ float4 sred[3][PR_ROWS][64];

    for (int i = threadIdx.x; i < PR_ROWS * 256; i += 256) {
        int r = i >> 8, c = i & 255;
        int rr = r0 + r;
        srow[r][c] = (rr < 4) ? ve[rr * 256 + c] : pe[(rr - 4) * 256 + c];
    }
    __syncthreads();

    float4 acc[PR_ROWS];
#pragma unroll
    for (int r = 0; r < PR_ROWS; r++) acc[r] = make_float4(0.f, 0.f, 0.f, 0.f);

    const float4* Wv = reinterpret_cast<const float4*>(Wt);
#pragma unroll 8
    for (int e = 0; e < 64; e++) {
        float4 w = Wv[(ebase + e) * 64 + o4];
#pragma unroll
        for (int r = 0; r < PR_ROWS; r++) {
            float x = srow[r][ebase + e];
            acc[r].x += x * w.x; acc[r].y += x * w.y;
            acc[r].z += x * w.z; acc[r].w += x * w.w;
        }
    }

    if (eh > 0) {
#pragma unroll
        for (int r = 0; r < PR_ROWS; r++) sred[eh - 1][r][o4] = acc[r];
    }
    __syncthreads();
    if (eh == 0) {
#pragma unroll
        for (int r = 0; r < PR_ROWS; r++) {
            float4 a = acc[r];
            float4 b0 = sred[0][r][o4], b1 = sred[1][r][o4], b2 = sred[2][r][o4];
            a.x += b0.x + b1.x + b2.x;
            a.y += b0.y + b1.y + b2.y;
            a.z += b0.z + b1.z + b2.z;
            a.w += b0.w + b1.w + b2.w;
            __half2* dst = reinterpret_cast<__half2*>(proj + (r0 + r) * 256 + o4 * 4);
            dst[0] = __floats2half2_rn(a.x, a.y);
            dst[1] = __floats2half2_rn(a.z, a.w);
        }
    }
}

// ---------------------------------------------------------------------------
// Kernel C: layers 0-2 (pure embedding sum), fp32 exact. (unchanged, passing)
// ---------------------------------------------------------------------------
__global__ void __launch_bounds__(256) embed_small_kernel(
    const int* __restrict__ value,
    const int* __restrict__ depth,
    const int* __restrict__ position,
    const float* __restrict__ v0, const float* __restrict__ v1, const float* __restrict__ v2,
    const float* __restrict__ p0, const float* __restrict__ p1, const float* __restrict__ p2,
    const float* __restrict__ d0, const float* __restrict__ d1, const float* __restrict__ d2,
    float* __restrict__ out)
{
    int idx = blockIdx.x * blockDim.x + threadIdx.x;
    int lane  = idx & 63;
    int token = idx >> 6;
    if (token >= BATCH * 584) return;
    int b = token / 584;
    int s = token % 584;

    const float *ve, *pe, *de;
    if (s < 8)       { ve = v0; pe = p0; de = d0; }
    else if (s < 72) { ve = v1; pe = p1; de = d1; }
    else             { ve = v2; pe = p2; de = d2; }

    int base = b * S_TOTAL + s;
    int v = value[base];
    int d = depth[base];
    const int* pp = position + base * 3;
    int q0 = pp[0], q1 = pp[1], q2 = pp[2];

    const float4* V  = reinterpret_cast<const float4*>(ve) + v * 64 + lane;
    const float4* P0 = reinterpret_cast<const float4*>(pe) + (q0)       * 64 + lane;
    const float4* P1 = reinterpret_cast<const float4*>(pe) + (64 + q1)  * 64 + lane;
    const float4* P2 = reinterpret_cast<const float4*>(pe) + (128 + q2) * 64 + lane;
    const float4* D  = reinterpret_cast<const float4*>(de) + d * 64 + lane;

    float4 a = *V, x;
    x = *P0; a.x += x.x; a.y += x.y; a.z += x.z; a.w += x.w;
    x = *P1; a.x += x.x; a.y += x.y; a.z += x.z; a.w += x.w;
    x = *P2; a.x += x.x; a.y += x.y; a.z += x.z; a.w += x.w;
    x = *D;  a.x += x.x; a.y += x.y; a.z += x.z; a.w += x.w;

    reinterpret_cast<float4*>(out)[(b * OUT_TOKENS + s) * 64 + lane] = a;
}

// ---------------------------------------------------------------------------
// Kernel D: conv layers via fp16 projected-table gathers.
// warp = one token: 32 lanes x 16B = one 512B fp16 row, coalesced.
// Indices fetched lane-parallel (2 LDGs/warp) and broadcast via shfl.
// The 4 rows per kk are summed with an HADD2 tree (12 HADD2), converted
// once, then accumulated in fp32 across kk.
// ---------------------------------------------------------------------------
__device__ __forceinline__ __half2 u2h2(unsigned u) {
    return *reinterpret_cast<const __half2*>(&u);
}

template <int K>
__global__ void __launch_bounds__(256) conv_half_kernel(
    const int* __restrict__ value,
    const int* __restrict__ position,
    const float* __restrict__ bias,
    float* __restrict__ out,
    int in_start, int out_row_start, int t_per_b)
{
    const __half* proj = (K == 4) ? g_proj3h : g_proj4h;

    int gwarp = (blockIdx.x * blockDim.x + threadIdx.x) >> 5;
    int lane  = threadIdx.x & 31;
    if (gwarp >= BATCH * t_per_b) return;
    int b = gwarp / t_per_b;
    int t = gwarp % t_per_b;

    int sbase = b * S_TOTAL + in_start + t * K;

    // Lane-parallel index fetch: values for kk=lane (<K), positions flat.
    int vload = (lane < K)     ? value[sbase + lane]          : 0;
    int pload = (lane < 3 * K) ? position[sbase * 3 + lane]   : 0;

    // 8 fp32 accumulators (o = lane*8 .. lane*8+7), init with bias
    float acc[8];
    {
        const float4* bv = reinterpret_cast<const float4*>(bias);
        float4 b0 = bv[lane * 2], b1 = bv[lane * 2 + 1];
        acc[0] = b0.x; acc[1] = b0.y; acc[2] = b0.z; acc[3] = b0.w;
        acc[4] = b1.x; acc[5] = b1.y; acc[6] = b1.z; acc[7] = b1.w;
    }

#pragma unroll
    for (int kk = 0; kk < K; kk++) {
        int v  = __shfl_sync(0xffffffffu, vload, kk);
        int q0 = __shfl_sync(0xffffffffu, pload, kk * 3 + 0);
        int q1 = __shfl_sync(0xffffffffu, pload, kk * 3 + 1);
        int q2 = __shfl_sync(0xffffffffu, pload, kk * 3 + 2);

        // Row stride = 256 halves = 32 uint4; lane picks its 16B chunk.
        const uint4* P = reinterpret_cast<const uint4*>(proj + kk * (NROWS * 256));
        uint4 u0 = P[v          * 32 + lane];
        uint4 u1 = P[(4   + q0) * 32 + lane];
        uint4 u2 = P[(68  + q1) * 32 + lane];
        uint4 u3 = P[(132 + q2) * 32 + lane];

        // HADD2 tree over the 4 rows, one conversion, fp32 accumulate.
        __half2 sx = __hadd2(__hadd2(u2h2(u0.x), u2h2(u1.x)),
                             __hadd2(u2h2(u2.x), u2h2(u3.x)));
        __half2 sy = __hadd2(__hadd2(u2h2(u0.y), u2h2(u1.y)),
                             __hadd2(u2h2(u2.y), u2h2(u3.y)));
        __half2 sz = __hadd2(__hadd2(u2h2(u0.z), u2h2(u1.z)),
                             __hadd2(u2h2(u2.z), u2h2(u3.z)));
        __half2 sw = __hadd2(__hadd2(u2h2(u0.w), u2h2(u1.w)),
                             __hadd2(u2h2(u2.w), u2h2(u3.w)));

        float2 f;
        f = __half22float2(sx); acc[0] += f.x; acc[1] += f.y;
        f = __half22float2(sy); acc[2] += f.x; acc[3] += f.y;
        f = __half22float2(sz); acc[4] += f.x; acc[5] += f.y;
        f = __half22float2(sw); acc[6] += f.x; acc[7] += f.y;
    }

    int row = b * OUT_TOKENS + out_row_start + t;
    float4* dst = reinterpret_cast<float4*>(out + row * 256 + lane * 8);
    dst[0] = make_float4(acc[0], acc[1], acc[2], acc[3]);
    dst[1] = make_float4(acc[4], acc[5], acc[6], acc[7]);
}

// ---------------------------------------------------------------------------
// Launch. Inputs classified BY ELEMENT COUNT (robust to metadata ordering).
// Launch order keeps conv4 in the ncu capture slot (same as R6).
// ---------------------------------------------------------------------------
extern "C" void kernel_launch(void* const* d_in, const int* in_sizes, int n_in,
                              void* d_out, int out_size) {
    const int* value = nullptr;
    const int* depth = nullptr;
    const int* position = nullptr;
    const float* val_emb[5] = {};
    const float* pos_emb[5] = {};
    const float* dep_emb[3] = {};
    const float* conv_w3 = nullptr;
    const float* conv_w4 = nullptr;
    const float* conv_b3 = nullptr;
    const float* conv_b4 = nullptr;

    int n_val = 0, n_pos = 0, n_dep = 0, n_cb = 0, n_vd = 0;
    for (int i = 0; i < n_in; i++) {
        int sz = in_sizes[i];
        const void* p = d_in[i];
        switch (sz) {
            case 299584:
                if (n_vd++ == 0) value = (const int*)p; else depth = (const int*)p;
                break;
            case 898752:  position = (const int*)p; break;
            case 1024:    if (n_val < 5) val_emb[n_val++] = (const float*)p; break;
            case 49152:   if (n_pos < 5) pos_emb[n_pos++] = (const float*)p; break;
            case 1536:    if (n_dep < 3) dep_emb[n_dep++] = (const float*)p; break;
            case 262144:  conv_w3 = (const float*)p; break;
            case 524288:  conv_w4 = (const float*)p; break;
            case 256:
                if (n_cb++ == 0) conv_b3 = (const float*)p; else conv_b4 = (const float*)p;
                break;
            default: break;
        }
    }

    float* out = (float*)d_out;

    // A: tiled transposes
    transpose_w_tiled<4><<<(256 / 64) * (256 / 32), 256>>>(conv_w3);
    transpose_w_tiled<8><<<(256 / 32) * (256 / 32), 256>>>(conv_w4);

    // B: fused projection -> fp16 tables (49 chunks x 12 slices)
    project_all_kernel<<<dim3(NROWS / PR_ROWS, 12), 256>>>(
        val_emb[3], pos_emb[3], val_emb[4], pos_emb[4]);

    // D4 (ncu capture slot): 32768 token-warps
    {
        int warps4 = BATCH * 4096;
        conv_half_kernel<8><<<(warps4 * 32 + 255) / 256, 256>>>(
            value, position, conv_b4, out,
            /*in_start=*/4680, /*out_row_start=*/1608, /*t_per_b=*/4096);
    }

    // D3: 8192 token-warps
    {
        int warps3 = BATCH * 1024;
        conv_half_kernel<4><<<(warps3 * 32 + 255) / 256, 256>>>(
            value, position, conv_b3, out,
            /*in_start=*/584, /*out_row_start=*/584, /*t_per_b=*/1024);
    }

    // C: small layers 0-2
    {
        int threads = BATCH * 584 * 64;
        embed_small_kernel<<<(threads + 255) / 256, 256>>>(
            value, depth, position,
            val_emb[0], val_emb[1], val_emb[2],
            pos_emb[0], pos_emb[1], pos_emb[2],
            dep_emb[0], dep_emb[1], dep_emb[2],
            out);
    }
}